// round 8
// baseline (speedup 1.0000x reference)
#include <cuda_runtime.h>
#include <cstdint>

#define TOPK      2000
#define NMS_THR   0.5f
#define MAXN      200000
#define MAXG      128
#define HBINS     65536
#define CAP       8192
#define CBLK      32          // ceil(TOPK/64)
#define BM        256         // proposals per block in main kernel
#define NCELLMAX  128         // max grid cells (11x7=77 typical)
#define CELLCAP   24          // max GT entries per cell

typedef unsigned long long ull;

// ---------------- scratch (no allocation allowed) ----------------
__device__ float               g_score[MAXN];
__device__ float4              g_boxper[MAXN];
__device__ __align__(16) int   g_hist[HBINS];    // zero at load; re-zeroed in compact
__device__ int                 g_candcount;      // zero at load; reset in sort
__device__ int                 g_binB;
__device__ ull                 g_cand[CAP];
__device__ float4              g_topboxes[TOPK];
__device__ ull                 g_mask[TOPK * CBLK];

// =================== K1: fused per-proposal (spatially pruned IoU) ========
__global__ void __launch_bounds__(BM) main_kernel(
        const float4* __restrict__ prop,
        const float4* __restrict__ btp,   // (N*C) float4
        const float*  __restrict__ cls,
        const float4* __restrict__ gt,
        const int* __restrict__ ihp,
        const int* __restrict__ iwp,
        float4* __restrict__ out,         // full output, rows (TOPK+n)
        int N, int C, int G)
{
    __shared__ float4        sgtb[MAXG];
    __shared__ float         sga[MAXG];
    __shared__ int           scnt[NCELLMAX];
    __shared__ unsigned char slist[NCELLMAX * CELLCAP];
    __shared__ int           soverflow;
    extern __shared__ float  scls[];      // BM*21 floats (stride 21 -> conflict-free)

    int tid = threadIdx.x;
    int n0  = blockIdx.x * BM;

    int vi = ihp[0];
    float H = (vi > 0 && vi < 1000000) ? (float)vi : __int_as_float(vi);
    vi = iwp[0];
    float W = (vi > 0 && vi < 1000000) ? (float)vi : __int_as_float(vi);

    // cell grid geometry (cell = 128px; both GTs and proposals are <=128px wide)
    int ncx = (int)((W + 127.0f) * 0.0078125f);
    int ncy = (int)((H + 127.0f) * 0.0078125f);
    bool useCells = (G <= MAXG) && (ncx >= 1) && (ncy >= 1) && (ncx * ncy <= NCELLMAX);

    for (int i = tid; i < G && i < MAXG; i += BM) {
        float4 g = gt[i];
        sgtb[i] = g;
        sga[i]  = (g.z - g.x) * (g.w - g.y);
    }
    if (tid < NCELLMAX) scnt[tid] = 0;
    if (tid == 0) soverflow = 0;
    // stage cls rows (coalesced global reads)
    {
        int rows = min(BM, N - n0);
        if (rows > 0) {
            const float* cbase = cls + (size_t)n0 * C;
            if (C == 21) {
                int total = rows * 21;
                for (int idx = tid; idx < total; idx += BM) {
                    int r = idx / 21;
                    scls[r * 21 + (idx - r * 21)] = cbase[idx];
                }
            } else {
                int total = rows * C;
                for (int idx = tid; idx < total; idx += BM) {
                    int r = idx / C;
                    scls[r * 21 + (idx - r * C)] = cbase[idx];
                }
            }
        }
    }
    __syncthreads();

    // build per-cell GT lists (thread g inserts gt g into its <=2x2 cells)
    if (useCells && tid < G) {
        float4 g = sgtb[tid];
        int cx0 = max(0, min((int)(g.x * 0.0078125f), ncx - 1));
        int cx1 = max(0, min((int)(g.z * 0.0078125f), ncx - 1));
        int cy0 = max(0, min((int)(g.y * 0.0078125f), ncy - 1));
        int cy1 = max(0, min((int)(g.w * 0.0078125f), ncy - 1));
        for (int cy = cy0; cy <= cy1; cy++)
            for (int cx = cx0; cx <= cx1; cx++) {
                int cell = cy * ncx + cx;
                int pos = atomicAdd(&scnt[cell], 1);
                if (pos < CELLCAP) slist[cell * CELLCAP + pos] = (unsigned char)tid;
                else soverflow = 1;
            }
    }
    __syncthreads();

    int n = n0 + tid;
    if (n >= N) return;

    float4 p = prop[n];
    float pw = p.z - p.x, ph = p.w - p.y;
    float pcx = p.x + 0.5f * pw, pcy = p.y + 0.5f * ph;
    float parea = pw * ph;

    // softmax score + fg argmax (from shared) — identical to passing R7 code
    const float* cr = scls + tid * 21;
    float m = cr[0], bl = -1e30f; int bc = 1;
    #pragma unroll
    for (int c = 1; c < 21; c++) {
        float v = cr[c];
        m = fmaxf(m, v);
        if (v > bl) { bl = v; bc = c; }
    }
    float Z = 0.f;
    #pragma unroll
    for (int c = 0; c < 21; c++) Z += __expf(cr[c] - m);
    float score = __fdividef(__expf(bl - m), Z);

    // decode selected class box, clamp
    float t_;
    float4 t = btp[(size_t)n * C + bc];
    float dcx = t.x * pw + pcx;
    float dcy = t.y * ph + pcy;
    float dw  = __expf(t.z) * pw;
    float dh  = __expf(t.w) * ph;
    float4 box;
    box.x = fminf(fmaxf(dcx - 0.5f * dw, 0.f), W);
    box.y = fminf(fmaxf(dcy - 0.5f * dh, 0.f), H);
    box.z = fminf(fmaxf(dcx + 0.5f * dw, 0.f), W);
    box.w = fminf(fmaxf(dcy + 0.5f * dh, 0.f), H);
    (void)t_;

    g_boxper[n] = box;
    g_score[n]  = score;
    atomicAdd(&g_hist[__float_as_uint(score) >> 16], 1);

    // best-IoU gt match
    #define IOU_STEP(gg, nn, dd, ii)                                   \
        {   float4 gb = sgtb[(gg)];                                    \
            float lx = fmaxf(gb.x, p.x);                               \
            float ly = fmaxf(gb.y, p.y);                               \
            float rx = fminf(gb.z, p.z);                               \
            float ry = fminf(gb.w, p.w);                               \
            float iw = fmaxf(rx - lx, 0.f), ihh = fmaxf(ry - ly, 0.f); \
            float inter = iw * ihh;                                    \
            float den = sga[(gg)] + parea - inter;                     \
            if (inter * (dd) > (nn) * den) { (nn) = inter; (dd) = den; (ii) = (gg); } }
    int bg = 0;
    if (useCells && !soverflow) {
        // pruned: only GTs sharing a cell with this proposal can have IoU>0.
        // bnum=0 init => all-zero rows yield bg=0, matching argmax semantics.
        float bnum = 0.f, bden = 1.f;
        int pcx0 = max(0, min((int)(p.x * 0.0078125f), ncx - 1));
        int pcx1 = max(0, min((int)(p.z * 0.0078125f), ncx - 1));
        int pcy0 = max(0, min((int)(p.y * 0.0078125f), ncy - 1));
        int pcy1 = max(0, min((int)(p.w * 0.0078125f), ncy - 1));
        for (int cy = pcy0; cy <= pcy1; cy++)
            for (int cx = pcx0; cx <= pcx1; cx++) {
                int cell = cy * ncx + cx;
                int cnt = min(scnt[cell], CELLCAP);
                const unsigned char* lp = slist + cell * CELLCAP;
                for (int k2 = 0; k2 < cnt; k2++) {
                    int g = lp[k2];
                    IOU_STEP(g, bnum, bden, bg);
                }
            }
    } else {
        // exact fallback: full ascending loop (strict >, first-max)
        float bnum = -1.f, bden = 1.f;
        for (int g = 0; g < G; g++) IOU_STEP(g, bnum, bden, bg);
    }
    #undef IOU_STEP

    float4 gb = sgtb[bg];
    float gw = gb.z - gb.x, gh = gb.w - gb.y;
    float gcx = gb.x + 0.5f * gw, gcy = gb.y + 0.5f * gh;
    float4 rt;
    rt.x = __fdividef(gcx - pcx, pw);
    rt.y = __fdividef(gcy - pcy, ph);
    rt.z = __logf(__fdividef(gw, pw));
    rt.w = __logf(__fdividef(gh, ph));
    out[TOPK + n] = rt;
}

// =================== K2: findbin, 1024 threads, warp-parallel fine walk ====
__global__ void __launch_bounds__(1024) findbin_kernel() {
    __shared__ int csum[1024];
    __shared__ int wsum[32];
    __shared__ int s_chunk, s_excl;
    int tid = threadIdx.x;
    int w = tid >> 5, lane = tid & 31;

    for (int c = w; c < 1024; c += 32) {
        int base = HBINS - (c + 1) * 64;
        int s = g_hist[base + lane] + g_hist[base + 32 + lane];
        s = __reduce_add_sync(0xFFFFFFFFu, s);
        if (lane == 0) csum[c] = s;
    }
    __syncthreads();

    int v = csum[tid];
    int x = v;
    #pragma unroll
    for (int o = 1; o < 32; o <<= 1) {
        int y = __shfl_up_sync(0xFFFFFFFFu, x, o);
        if (lane >= o) x += y;
    }
    if (lane == 31) wsum[w] = x;
    __syncthreads();
    if (w == 0) {
        int s = wsum[lane];
        #pragma unroll
        for (int o = 1; o < 32; o <<= 1) {
            int y = __shfl_up_sync(0xFFFFFFFFu, s, o);
            if (lane >= o) s += y;
        }
        wsum[lane] = s;
    }
    __syncthreads();
    int incl = x + ((w > 0) ? wsum[w - 1] : 0);
    int excl = incl - v;
    if (excl < TOPK && incl >= TOPK) { s_chunk = tid; s_excl = excl; }
    __syncthreads();

    if (w == 0) {
        int chunk = s_chunk, be = s_excl;
        int base = HBINS - (chunk + 1) * 64;
        int x0 = g_hist[base + 63 - lane];
        int x1 = g_hist[base + 31 - lane];
        int s0 = x0;
        #pragma unroll
        for (int o = 1; o < 32; o <<= 1) {
            int y = __shfl_up_sync(0xFFFFFFFFu, s0, o);
            if (lane >= o) s0 += y;
        }
        int t0 = __shfl_sync(0xFFFFFFFFu, s0, 31);
        int s1 = x1;
        #pragma unroll
        for (int o = 1; o < 32; o <<= 1) {
            int y = __shfl_up_sync(0xFFFFFFFFu, s1, o);
            if (lane >= o) s1 += y;
        }
        int incl0 = be + s0, excl0 = incl0 - x0;
        if (excl0 < TOPK && incl0 >= TOPK) g_binB = base + 63 - lane;
        int incl1 = be + t0 + s1, excl1 = incl1 - x1;
        if (excl1 < TOPK && incl1 >= TOPK) g_binB = base + 31 - lane;
    }
}

// =================== K3: compact + hist re-zero ============
__global__ void __launch_bounds__(256) compact_kernel(int N) {
    int gid = blockIdx.x * 256 + threadIdx.x;
    if (gid < N) {
        unsigned bits = __float_as_uint(g_score[gid]);
        if ((int)(bits >> 16) >= g_binB) {
            int pos = atomicAdd(&g_candcount, 1);
            if (pos < CAP)
                g_cand[pos] = ((ull)bits << 32) | (unsigned)(~gid);
        }
    }
    if (gid < HBINS) g_hist[gid] = 0;      // parallel re-zero for next replay
}

// bitonic shfl pass on a register-resident element (j <= 16, intra-warp)
__device__ __forceinline__ void shfl_pass(ull& v, int i, int j, int k) {
    ull wv = __shfl_xor_sync(0xFFFFFFFFu, v, j);
    bool desc  = ((i & k) == 0);
    bool lower = ((i & j) == 0);
    bool takeMax = (desc == lower);
    bool gt = v > wv;
    v = (takeMax == gt) ? v : wv;
}

__device__ __forceinline__ void safe_gather(int pos, ull key) {
    unsigned n = ~(unsigned)(key & 0xFFFFFFFFULL);
    if (n >= MAXN) n = 0;                  // defensive: never OOB
    g_topboxes[pos] = g_boxper[n];
}

// =================== K4: bitonic sort (regs+shfl inner passes) ============
__global__ void __launch_bounds__(1024) sort_kernel() {
    extern __shared__ ull sk[];
    int t = threadIdx.x;
    int M = g_candcount; if (M > CAP) M = CAP;
    __syncthreads();                       // ALL threads read candcount first
    if (t == 0) g_candcount = 0;           // then reset for next replay
    int P = 2048;
    while (P < M) P <<= 1;

    if (P == 2048) {
        const int i0 = t, i1 = t + 1024;
        ull v0 = (i0 < M) ? g_cand[i0] : 0ULL;
        ull v1 = (i1 < M) ? g_cand[i1] : 0ULL;
        #pragma unroll
        for (int k = 2; k <= 32; k <<= 1)
            #pragma unroll
            for (int j = k >> 1; j > 0; j >>= 1) {
                shfl_pass(v0, i0, j, k);
                shfl_pass(v1, i1, j, k);
            }
        for (int k = 64; k <= 2048; k <<= 1) {
            sk[i0] = v0; sk[i1] = v1;
            __syncthreads();
            for (int j = k >> 1; j >= 32; j >>= 1) {
                #pragma unroll
                for (int e = 0; e < 2; e++) {
                    int i = t + (e << 10);
                    int l = i ^ j;
                    if (l > i) {
                        bool desc = ((i & k) == 0);
                        ull a = sk[i], b = sk[l];
                        if (desc ? (a < b) : (a > b)) { sk[i] = b; sk[l] = a; }
                    }
                }
                __syncthreads();
            }
            v0 = sk[i0]; v1 = sk[i1];
            #pragma unroll
            for (int j = 16; j > 0; j >>= 1) {
                shfl_pass(v0, i0, j, k);
                shfl_pass(v1, i1, j, k);
            }
        }
        if (i0 < TOPK) safe_gather(i0, v0);
        if (i1 < TOPK) safe_gather(i1, v1);
    } else {
        int epw = P >> 10;
        for (int e = 0; e < epw; e++) {
            int i = t + (e << 10);
            sk[i] = (i < M) ? g_cand[i] : 0ULL;
        }
        __syncthreads();
        for (int k = 2; k <= P; k <<= 1)
            for (int j = k >> 1; j > 0; j >>= 1) {
                for (int e = 0; e < epw; e++) {
                    int i = t + (e << 10);
                    int l = i ^ j;
                    if (l > i) {
                        bool desc = ((i & k) == 0);
                        ull a = sk[i], b = sk[l];
                        if (desc ? (a < b) : (a > b)) { sk[i] = b; sk[l] = a; }
                    }
                }
                __syncthreads();
            }
        for (int i = t; i < TOPK; i += 1024) safe_gather(i, sk[i]);
    }
}

// =================== K5: NMS suppression bitmask ==========================
__global__ void __launch_bounds__(256) nms_mask_kernel() {
    __shared__ float4 sb[64];
    int cb = blockIdx.x;
    int t  = threadIdx.x;
    int col0 = cb * 64;
    if (t < 64 && col0 + t < TOPK) sb[t] = g_topboxes[col0 + t];
    __syncthreads();
    int row = blockIdx.y * 256 + t;
    if (row >= TOPK) return;
    float4 a = g_topboxes[row];
    float aarea = (a.z - a.x) * (a.w - a.y);
    ull bits = 0;
    int nj = min(64, TOPK - col0);
    for (int j = 0; j < nj; j++) {
        float4 b = sb[j];
        float lx = fmaxf(a.x, b.x), ly = fmaxf(a.y, b.y);
        float rx = fminf(a.z, b.z), ry = fminf(a.w, b.w);
        float iw = fmaxf(rx - lx, 0.f), ih = fmaxf(ry - ly, 0.f);
        float inter = iw * ih;
        float barea = (b.z - b.x) * (b.w - b.y);
        float iou = __fdividef(inter, aarea + barea - inter);
        if (iou > NMS_THR) bits |= (1ULL << j);   // NaN compares false
    }
    g_mask[row * CBLK + cb] = bits;
}

// =================== K6: greedy scan + final write ========================
__global__ void __launch_bounds__(256) nms_final_kernel(float* __restrict__ out) {
    __shared__ ull skeep[CBLK];
    int t = threadIdx.x;
    if (t < 32) {
        ull rem = 0;
        ull cur_sup = 0;
        ull kw = 0;
        ull bit = 1;
        const int D = 16;
        ull buf[D];
        #pragma unroll
        for (int k = 0; k < D; k++) buf[k] = g_mask[k * CBLK + t];
        ull m0 = __shfl_sync(0xFFFFFFFFu, buf[0], 0);
        ull m1 = __shfl_sync(0xFFFFFFFFu, buf[1], 0);
        ull m2 = __shfl_sync(0xFFFFFFFFu, buf[2], 0);
        ull m3 = __shfl_sync(0xFFFFFFFFu, buf[3], 0);
        for (int i = 0; i < TOPK; i++) {
            ull cur = buf[i & (D - 1)];
            ull mn = 0;
            if (i + 4 < TOPK)
                mn = __shfl_sync(0xFFFFFFFFu, buf[(i + 4) & (D - 1)], (i + 4) >> 6);
            if (i + D < TOPK) buf[i & (D - 1)] = g_mask[(i + D) * CBLK + t];

            bool keep = (cur_sup & bit) == 0ULL;
            if (keep) { cur_sup |= m0; kw |= bit; }
            rem |= keep ? cur : 0ULL;

            if ((i & 63) == 63) {
                if (t == 0) skeep[i >> 6] = kw;
                kw = 0; bit = 1;
                cur_sup = __shfl_sync(0xFFFFFFFFu, rem, (i + 1) >> 6);
            } else {
                bit <<= 1;
            }
            m0 = m1; m1 = m2; m2 = m3; m3 = mn;
        }
        if (t == 0) skeep[(TOPK - 1) >> 6] = kw;
    }
    __syncthreads();
    const float* tb = (const float*)g_topboxes;
    for (int idx = t; idx < TOPK * 4; idx += 256) {
        int r = idx >> 2;
        float k = ((skeep[r >> 6] >> (r & 63)) & 1ULL) ? 1.0f : 0.0f;
        out[idx] = tb[idx] * k;
    }
}

// ---------------- launcher: 6 graph nodes ----------------
extern "C" void kernel_launch(void* const* d_in, const int* in_sizes, int n_in,
                              void* d_out, int out_size)
{
    const float4* prop = (const float4*)d_in[0];
    const float4* btp  = (const float4*)d_in[1];
    const float*  cls  = (const float*)d_in[2];
    const float4* gt   = (const float4*)d_in[3];
    const int*    ih   = (const int*)d_in[4];
    const int*    iw   = (const int*)d_in[5];
    float*        out  = (float*)d_out;

    int N = in_sizes[0] / 4;
    int C = in_sizes[2] / N;
    int G = in_sizes[3] / 4;

    static int smem_set = 0;
    if (!smem_set) {
        cudaFuncSetAttribute(sort_kernel,
                             cudaFuncAttributeMaxDynamicSharedMemorySize,
                             CAP * (int)sizeof(ull));
        smem_set = 1;
    }

    int smem_main = BM * 21 * (int)sizeof(float);
    main_kernel<<<(N + BM - 1) / BM, BM, smem_main>>>(
        prop, btp, cls, gt, ih, iw, (float4*)out, N, C, G);

    findbin_kernel<<<1, 1024>>>();
    compact_kernel<<<(N + 255) / 256, 256>>>(N);
    sort_kernel<<<1, 1024, CAP * sizeof(ull)>>>();

    dim3 grid((TOPK + 63) / 64, (TOPK + 255) / 256);
    nms_mask_kernel<<<grid, 256>>>();
    nms_final_kernel<<<1, 256>>>(out);
}

// round 9
// speedup vs baseline: 1.0294x; 1.0294x over previous
#include <cuda_runtime.h>
#include <cstdint>

#define TOPK      2000
#define NMS_THR   0.5f
#define MAXN      200000
#define MAXG      128
#define HBINS     65536
#define CAP       8192
#define CBLK      32          // ceil(TOPK/64)
#define BM        256         // proposals per block in main kernel
#define NCELLMAX  128         // max grid cells (11x7=77 typical)
#define CELLCAP   24          // max GT entries per cell

typedef unsigned long long ull;

// ---------------- scratch (no allocation allowed) ----------------
__device__ float               g_score[MAXN];
__device__ unsigned char       g_cls[MAXN];
__device__ __align__(16) int   g_hist[HBINS];    // zero at load; re-zeroed in compact
__device__ int                 g_candcount;      // zero at load; reset in sort
__device__ int                 g_binB;
__device__ ull                 g_cand[CAP];
__device__ int                 g_topidx[TOPK];
__device__ float4              g_topboxes[TOPK];
__device__ ull                 g_mask[TOPK * CBLK];

// =================== K1: per-proposal scores + reg_targets (no decode) ====
__global__ void __launch_bounds__(BM) main_kernel(
        const float4* __restrict__ prop,
        const float*  __restrict__ cls,
        const float4* __restrict__ gt,
        const int* __restrict__ ihp,
        const int* __restrict__ iwp,
        float4* __restrict__ out,         // full output, rows (TOPK+n)
        int N, int C, int G)
{
    __shared__ float4        sgtb[MAXG];
    __shared__ float         sga[MAXG];
    __shared__ int           scnt[NCELLMAX];
    __shared__ unsigned char slist[NCELLMAX * CELLCAP];
    __shared__ int           soverflow;
    extern __shared__ float  scls[];      // BM*21 floats (stride 21 -> conflict-free)

    int tid = threadIdx.x;
    int n0  = blockIdx.x * BM;

    int vi = ihp[0];
    float H = (vi > 0 && vi < 1000000) ? (float)vi : __int_as_float(vi);
    vi = iwp[0];
    float W = (vi > 0 && vi < 1000000) ? (float)vi : __int_as_float(vi);
    (void)H; (void)W;

    // cell grid geometry (cell = 128px; boxes are <=128px wide)
    int ncx = (int)((W + 127.0f) * 0.0078125f);
    int ncy = (int)((H + 127.0f) * 0.0078125f);
    bool useCells = (G <= MAXG) && (ncx >= 1) && (ncy >= 1) && (ncx * ncy <= NCELLMAX);

    for (int i = tid; i < G && i < MAXG; i += BM) {
        float4 g = gt[i];
        sgtb[i] = g;
        sga[i]  = (g.z - g.x) * (g.w - g.y);
    }
    if (tid < NCELLMAX) scnt[tid] = 0;
    if (tid == 0) soverflow = 0;
    // stage cls rows (coalesced global reads)
    {
        int rows = min(BM, N - n0);
        if (rows > 0) {
            const float* cbase = cls + (size_t)n0 * C;
            if (C == 21) {
                int total = rows * 21;
                for (int idx = tid; idx < total; idx += BM) {
                    int r = idx / 21;
                    scls[r * 21 + (idx - r * 21)] = cbase[idx];
                }
            } else {
                int total = rows * C;
                for (int idx = tid; idx < total; idx += BM) {
                    int r = idx / C;
                    scls[r * 21 + (idx - r * C)] = cbase[idx];
                }
            }
        }
    }
    __syncthreads();

    // build per-cell GT lists (thread g inserts gt g into its <=2x2 cells)
    if (useCells && tid < G) {
        float4 g = sgtb[tid];
        int cx0 = max(0, min((int)(g.x * 0.0078125f), ncx - 1));
        int cx1 = max(0, min((int)(g.z * 0.0078125f), ncx - 1));
        int cy0 = max(0, min((int)(g.y * 0.0078125f), ncy - 1));
        int cy1 = max(0, min((int)(g.w * 0.0078125f), ncy - 1));
        for (int cy = cy0; cy <= cy1; cy++)
            for (int cx = cx0; cx <= cx1; cx++) {
                int cell = cy * ncx + cx;
                int pos = atomicAdd(&scnt[cell], 1);
                if (pos < CELLCAP) slist[cell * CELLCAP + pos] = (unsigned char)tid;
                else soverflow = 1;
            }
    }
    __syncthreads();

    int n = n0 + tid;
    if (n >= N) return;

    float4 p = prop[n];
    float pw = p.z - p.x, ph = p.w - p.y;
    float pcx = p.x + 0.5f * pw, pcy = p.y + 0.5f * ph;
    float parea = pw * ph;

    // softmax score + fg argmax (from shared)
    const float* cr = scls + tid * 21;
    float m = cr[0], bl = -1e30f; int bc = 1;
    #pragma unroll
    for (int c = 1; c < 21; c++) {
        float v = cr[c];
        m = fmaxf(m, v);
        if (v > bl) { bl = v; bc = c; }
    }
    float Z = 0.f;
    #pragma unroll
    for (int c = 0; c < 21; c++) Z += __expf(cr[c] - m);
    float score = __fdividef(__expf(bl - m), Z);

    g_score[n] = score;
    g_cls[n]   = (unsigned char)bc;
    atomicAdd(&g_hist[__float_as_uint(score) >> 16], 1);

    // best-IoU gt match
    #define IOU_STEP(gg, nn, dd, ii)                                   \
        {   float4 gb = sgtb[(gg)];                                    \
            float lx = fmaxf(gb.x, p.x);                               \
            float ly = fmaxf(gb.y, p.y);                               \
            float rx = fminf(gb.z, p.z);                               \
            float ry = fminf(gb.w, p.w);                               \
            float iw = fmaxf(rx - lx, 0.f), ihh = fmaxf(ry - ly, 0.f); \
            float inter = iw * ihh;                                    \
            float den = sga[(gg)] + parea - inter;                     \
            if (inter * (dd) > (nn) * den) { (nn) = inter; (dd) = den; (ii) = (gg); } }
    int bg = 0;
    if (useCells && !soverflow) {
        float bnum = 0.f, bden = 1.f;
        int pcx0 = max(0, min((int)(p.x * 0.0078125f), ncx - 1));
        int pcx1 = max(0, min((int)(p.z * 0.0078125f), ncx - 1));
        int pcy0 = max(0, min((int)(p.y * 0.0078125f), ncy - 1));
        int pcy1 = max(0, min((int)(p.w * 0.0078125f), ncy - 1));
        for (int cy = pcy0; cy <= pcy1; cy++)
            for (int cx = pcx0; cx <= pcx1; cx++) {
                int cell = cy * ncx + cx;
                int cnt = min(scnt[cell], CELLCAP);
                const unsigned char* lp = slist + cell * CELLCAP;
                for (int k2 = 0; k2 < cnt; k2++) {
                    int g = lp[k2];
                    IOU_STEP(g, bnum, bden, bg);
                }
            }
    } else {
        float bnum = -1.f, bden = 1.f;
        for (int g = 0; g < G; g++) IOU_STEP(g, bnum, bden, bg);
    }
    #undef IOU_STEP

    float4 gb = sgtb[bg];
    float gw = gb.z - gb.x, gh = gb.w - gb.y;
    float gcx = gb.x + 0.5f * gw, gcy = gb.y + 0.5f * gh;
    float4 rt;
    rt.x = __fdividef(gcx - pcx, pw);
    rt.y = __fdividef(gcy - pcy, ph);
    rt.z = __logf(__fdividef(gw, pw));
    rt.w = __logf(__fdividef(gh, ph));
    out[TOPK + n] = rt;
}

// =================== K2: findbin, 1024 threads, warp-parallel fine walk ====
__global__ void __launch_bounds__(1024) findbin_kernel() {
    __shared__ int csum[1024];
    __shared__ int wsum[32];
    __shared__ int s_chunk, s_excl;
    int tid = threadIdx.x;
    int w = tid >> 5, lane = tid & 31;

    for (int c = w; c < 1024; c += 32) {
        int base = HBINS - (c + 1) * 64;
        int s = g_hist[base + lane] + g_hist[base + 32 + lane];
        s = __reduce_add_sync(0xFFFFFFFFu, s);
        if (lane == 0) csum[c] = s;
    }
    __syncthreads();

    int v = csum[tid];
    int x = v;
    #pragma unroll
    for (int o = 1; o < 32; o <<= 1) {
        int y = __shfl_up_sync(0xFFFFFFFFu, x, o);
        if (lane >= o) x += y;
    }
    if (lane == 31) wsum[w] = x;
    __syncthreads();
    if (w == 0) {
        int s = wsum[lane];
        #pragma unroll
        for (int o = 1; o < 32; o <<= 1) {
            int y = __shfl_up_sync(0xFFFFFFFFu, s, o);
            if (lane >= o) s += y;
        }
        wsum[lane] = s;
    }
    __syncthreads();
    int incl = x + ((w > 0) ? wsum[w - 1] : 0);
    int excl = incl - v;
    if (excl < TOPK && incl >= TOPK) { s_chunk = tid; s_excl = excl; }
    __syncthreads();

    if (w == 0) {
        int chunk = s_chunk, be = s_excl;
        int base = HBINS - (chunk + 1) * 64;
        int x0 = g_hist[base + 63 - lane];
        int x1 = g_hist[base + 31 - lane];
        int s0 = x0;
        #pragma unroll
        for (int o = 1; o < 32; o <<= 1) {
            int y = __shfl_up_sync(0xFFFFFFFFu, s0, o);
            if (lane >= o) s0 += y;
        }
        int t0 = __shfl_sync(0xFFFFFFFFu, s0, 31);
        int s1 = x1;
        #pragma unroll
        for (int o = 1; o < 32; o <<= 1) {
            int y = __shfl_up_sync(0xFFFFFFFFu, s1, o);
            if (lane >= o) s1 += y;
        }
        int incl0 = be + s0, excl0 = incl0 - x0;
        if (excl0 < TOPK && incl0 >= TOPK) g_binB = base + 63 - lane;
        int incl1 = be + t0 + s1, excl1 = incl1 - x1;
        if (excl1 < TOPK && incl1 >= TOPK) g_binB = base + 31 - lane;
    }
}

// =================== K3: compact + hist re-zero ============
__global__ void __launch_bounds__(256) compact_kernel(int N) {
    int gid = blockIdx.x * 256 + threadIdx.x;
    if (gid < N) {
        unsigned bits = __float_as_uint(g_score[gid]);
        if ((int)(bits >> 16) >= g_binB) {
            int pos = atomicAdd(&g_candcount, 1);
            if (pos < CAP)
                g_cand[pos] = ((ull)bits << 32) | (unsigned)(~gid);
        }
    }
    if (gid < HBINS) g_hist[gid] = 0;      // parallel re-zero for next replay
}

// bitonic shfl pass on a register-resident element (j <= 16, intra-warp)
__device__ __forceinline__ void shfl_pass(ull& v, int i, int j, int k) {
    ull wv = __shfl_xor_sync(0xFFFFFFFFu, v, j);
    bool desc  = ((i & k) == 0);
    bool lower = ((i & j) == 0);
    bool takeMax = (desc == lower);
    bool gt = v > wv;
    v = (takeMax == gt) ? v : wv;
}

__device__ __forceinline__ void store_topidx(int pos, ull key) {
    unsigned n = ~(unsigned)(key & 0xFFFFFFFFULL);
    if (n >= MAXN) n = 0;                  // defensive: never OOB
    g_topidx[pos] = (int)n;
}

// =================== K4: bitonic sort (regs+shfl inner passes) ============
__global__ void __launch_bounds__(1024) sort_kernel() {
    extern __shared__ ull sk[];
    int t = threadIdx.x;
    int M = g_candcount; if (M > CAP) M = CAP;
    __syncthreads();                       // ALL threads read candcount first
    if (t == 0) g_candcount = 0;           // then reset for next replay
    int P = 2048;
    while (P < M) P <<= 1;

    if (P == 2048) {
        const int i0 = t, i1 = t + 1024;
        ull v0 = (i0 < M) ? g_cand[i0] : 0ULL;
        ull v1 = (i1 < M) ? g_cand[i1] : 0ULL;
        #pragma unroll
        for (int k = 2; k <= 32; k <<= 1)
            #pragma unroll
            for (int j = k >> 1; j > 0; j >>= 1) {
                shfl_pass(v0, i0, j, k);
                shfl_pass(v1, i1, j, k);
            }
        for (int k = 64; k <= 2048; k <<= 1) {
            sk[i0] = v0; sk[i1] = v1;
            __syncthreads();
            for (int j = k >> 1; j >= 32; j >>= 1) {
                #pragma unroll
                for (int e = 0; e < 2; e++) {
                    int i = t + (e << 10);
                    int l = i ^ j;
                    if (l > i) {
                        bool desc = ((i & k) == 0);
                        ull a = sk[i], b = sk[l];
                        if (desc ? (a < b) : (a > b)) { sk[i] = b; sk[l] = a; }
                    }
                }
                __syncthreads();
            }
            v0 = sk[i0]; v1 = sk[i1];
            #pragma unroll
            for (int j = 16; j > 0; j >>= 1) {
                shfl_pass(v0, i0, j, k);
                shfl_pass(v1, i1, j, k);
            }
        }
        if (i0 < TOPK) store_topidx(i0, v0);
        if (i1 < TOPK) store_topidx(i1, v1);
    } else {
        int epw = P >> 10;
        for (int e = 0; e < epw; e++) {
            int i = t + (e << 10);
            sk[i] = (i < M) ? g_cand[i] : 0ULL;
        }
        __syncthreads();
        for (int k = 2; k <= P; k <<= 1)
            for (int j = k >> 1; j > 0; j >>= 1) {
                for (int e = 0; e < epw; e++) {
                    int i = t + (e << 10);
                    int l = i ^ j;
                    if (l > i) {
                        bool desc = ((i & k) == 0);
                        ull a = sk[i], b = sk[l];
                        if (desc ? (a < b) : (a > b)) { sk[i] = b; sk[l] = a; }
                    }
                }
                __syncthreads();
            }
        for (int i = t; i < TOPK; i += 1024) store_topidx(i, sk[i]);
    }
}

// =================== K5: decode only the 2000 winners ======================
__global__ void __launch_bounds__(256) decode_kernel(
        const float4* __restrict__ prop,
        const float4* __restrict__ btp,
        const int* __restrict__ ihp,
        const int* __restrict__ iwp,
        int C)
{
    int i = blockIdx.x * 256 + threadIdx.x;
    if (i >= TOPK) return;
    int vi = ihp[0];
    float H = (vi > 0 && vi < 1000000) ? (float)vi : __int_as_float(vi);
    vi = iwp[0];
    float W = (vi > 0 && vi < 1000000) ? (float)vi : __int_as_float(vi);

    int n = g_topidx[i];
    int bc = (int)g_cls[n];
    float4 p = prop[n];
    float pw = p.z - p.x, ph = p.w - p.y;
    float pcx = p.x + 0.5f * pw, pcy = p.y + 0.5f * ph;

    float4 t = btp[(size_t)n * C + bc];
    float dcx = t.x * pw + pcx;
    float dcy = t.y * ph + pcy;
    float dw  = __expf(t.z) * pw;
    float dh  = __expf(t.w) * ph;
    float4 box;
    box.x = fminf(fmaxf(dcx - 0.5f * dw, 0.f), W);
    box.y = fminf(fmaxf(dcy - 0.5f * dh, 0.f), H);
    box.z = fminf(fmaxf(dcx + 0.5f * dw, 0.f), W);
    box.w = fminf(fmaxf(dcy + 0.5f * dh, 0.f), H);
    g_topboxes[i] = box;
}

// =================== K6: NMS suppression bitmask (upper triangle only) =====
__global__ void __launch_bounds__(256) nms_mask_kernel() {
    __shared__ float4 sb[64];
    int cb  = blockIdx.x;
    int rby = blockIdx.y;
    // lower-triangle blocks produce mask words never consumed by the scan
    if (cb * 64 + 63 < rby * 256) return;
    int t = threadIdx.x;
    int col0 = cb * 64;
    if (t < 64 && col0 + t < TOPK) sb[t] = g_topboxes[col0 + t];
    __syncthreads();
    int row = rby * 256 + t;
    if (row >= TOPK) return;
    float4 a = g_topboxes[row];
    float aarea = (a.z - a.x) * (a.w - a.y);
    ull bits = 0;
    int nj = min(64, TOPK - col0);
    for (int j = 0; j < nj; j++) {
        float4 b = sb[j];
        float lx = fmaxf(a.x, b.x), ly = fmaxf(a.y, b.y);
        float rx = fminf(a.z, b.z), ry = fminf(a.w, b.w);
        float iw = fmaxf(rx - lx, 0.f), ih = fmaxf(ry - ly, 0.f);
        float inter = iw * ih;
        float barea = (b.z - b.x) * (b.w - b.y);
        float iou = __fdividef(inter, aarea + barea - inter);
        if (iou > NMS_THR) bits |= (1ULL << j);   // NaN compares false
    }
    g_mask[row * CBLK + cb] = bits;
}

// =================== K7: greedy scan + final write ========================
__global__ void __launch_bounds__(256) nms_final_kernel(float* __restrict__ out) {
    __shared__ ull skeep[CBLK];
    int t = threadIdx.x;
    if (t < 32) {
        ull rem = 0;
        ull cur_sup = 0;
        ull kw = 0;
        ull bit = 1;
        const int D = 16;
        ull buf[D];
        #pragma unroll
        for (int k = 0; k < D; k++) buf[k] = g_mask[k * CBLK + t];
        ull m0 = __shfl_sync(0xFFFFFFFFu, buf[0], 0);
        ull m1 = __shfl_sync(0xFFFFFFFFu, buf[1], 0);
        ull m2 = __shfl_sync(0xFFFFFFFFu, buf[2], 0);
        ull m3 = __shfl_sync(0xFFFFFFFFu, buf[3], 0);
        for (int i = 0; i < TOPK; i++) {
            ull cur = buf[i & (D - 1)];
            ull mn = 0;
            if (i + 4 < TOPK)
                mn = __shfl_sync(0xFFFFFFFFu, buf[(i + 4) & (D - 1)], (i + 4) >> 6);
            if (i + D < TOPK) buf[i & (D - 1)] = g_mask[(i + D) * CBLK + t];

            bool keep = (cur_sup & bit) == 0ULL;
            if (keep) { cur_sup |= m0; kw |= bit; }
            rem |= keep ? cur : 0ULL;

            if ((i & 63) == 63) {
                if (t == 0) skeep[i >> 6] = kw;
                kw = 0; bit = 1;
                cur_sup = __shfl_sync(0xFFFFFFFFu, rem, (i + 1) >> 6);
            } else {
                bit <<= 1;
            }
            m0 = m1; m1 = m2; m2 = m3; m3 = mn;
        }
        if (t == 0) skeep[(TOPK - 1) >> 6] = kw;
    }
    __syncthreads();
    const float* tb = (const float*)g_topboxes;
    for (int idx = t; idx < TOPK * 4; idx += 256) {
        int r = idx >> 2;
        float k = ((skeep[r >> 6] >> (r & 63)) & 1ULL) ? 1.0f : 0.0f;
        out[idx] = tb[idx] * k;
    }
}

// ---------------- launcher: 7 graph nodes ----------------
extern "C" void kernel_launch(void* const* d_in, const int* in_sizes, int n_in,
                              void* d_out, int out_size)
{
    const float4* prop = (const float4*)d_in[0];
    const float4* btp  = (const float4*)d_in[1];
    const float*  cls  = (const float*)d_in[2];
    const float4* gt   = (const float4*)d_in[3];
    const int*    ih   = (const int*)d_in[4];
    const int*    iw   = (const int*)d_in[5];
    float*        out  = (float*)d_out;

    int N = in_sizes[0] / 4;
    int C = in_sizes[2] / N;
    int G = in_sizes[3] / 4;

    static int smem_set = 0;
    if (!smem_set) {
        cudaFuncSetAttribute(sort_kernel,
                             cudaFuncAttributeMaxDynamicSharedMemorySize,
                             CAP * (int)sizeof(ull));
        smem_set = 1;
    }

    int smem_main = BM * 21 * (int)sizeof(float);
    main_kernel<<<(N + BM - 1) / BM, BM, smem_main>>>(
        prop, cls, gt, ih, iw, (float4*)out, N, C, G);

    findbin_kernel<<<1, 1024>>>();
    compact_kernel<<<(N + 255) / 256, 256>>>(N);
    sort_kernel<<<1, 1024, CAP * sizeof(ull)>>>();
    decode_kernel<<<(TOPK + 255) / 256, 256>>>(prop, btp, ih, iw, C);

    dim3 grid((TOPK + 63) / 64, (TOPK + 255) / 256);
    nms_mask_kernel<<<grid, 256>>>();
    nms_final_kernel<<<1, 256>>>(out);
}